// round 13
// baseline (speedup 1.0000x reference)
#include <cuda_runtime.h>
#include <math.h>

#define BB 64
#define HH 512
#define EE 512
#define SS 2048
#define VV 32000
#define NSPLIT 32
#define SPLIT_S (SS / NSPLIT)      // 64
#define NCLS_TILES 250             // 32000 / 128
#define NCLSH (NCLS_TILES * 2)     // 500 k-split whales in mega
#define NATTN (NSPLIT * BB)        // 2048

#define FMA_F32X2(d, a, b, c) \
    asm("fma.rn.f32x2 %0, %1, %2, %3;" : "=l"(d) : "l"(a), "l"(b), "l"(c))
#define PACK_BCAST(d, f) \
    asm("mov.b64 %0, {%1, %1};" : "=l"(d) : "r"(__float_as_uint(f)))

typedef unsigned long long u64;

// ---------------- scratch ----------------
__device__ float g_gi[2 * BB * 3 * HH];     // 2 k-split partials
__device__ float g_gh[2 * BB * 3 * HH];
__device__ float g_A[BB * 2 * HH];          // [h_new | context]
__device__ float g_upart[4 * BB * HH];      // k-split partials of u
__device__ float g_pctx[(size_t)NSPLIT * BB * HH];
__device__ float g_pml[NSPLIT * BB * 2];
__device__ float g_ph[(size_t)BB * VV];     // h-half  logit partial (k 256..512)
__device__ float g_p0[(size_t)BB * VV];     // ctx-half logit partial (k 512..768)
__device__ float g_p1[(size_t)BB * VV];     // ctx-half logit partial (k 768..1024)

// ---------------- gemmN64: 64M x 64N tile, 128 thr, f32x2 ------------------
// BT=true : W[n][k].  BT=false: W[k][n].  GATHER: A row = relu(emb[idx[m]]).
template<bool BT, bool GATHER>
__device__ __forceinline__ void gemmN64(const float* __restrict__ A, int lda,
                                        const float* __restrict__ W, int ldw,
                                        float* __restrict__ C, int ldc,
                                        int K, int n0, const int* __restrict__ gidx) {
    __shared__ float As[2][16][68];
    __shared__ float Bs[2][16][68];
    const int tid = threadIdx.x;
    const int mt = (tid >> 4) * 8;   // 0..56
    const int nt = (tid & 15) * 4;   // 0..60

    u64 acc2[8][2];
#pragma unroll
    for (int i = 0; i < 8; i++) { acc2[i][0] = 0ull; acc2[i][1] = 0ull; }

    float4 ra[2], rb[2];
    auto ldG = [&](int k0) {
#pragma unroll
        for (int r = 0; r < 2; r++) {
            int i = tid + r * 128;
            int m = i >> 2, kq = (i & 3) * 4;
            int row = GATHER ? gidx[m] : m;
            ra[r] = *(const float4*)(A + (size_t)row * lda + k0 + kq);
            if (GATHER) {
                ra[r].x = fmaxf(ra[r].x, 0.f); ra[r].y = fmaxf(ra[r].y, 0.f);
                ra[r].z = fmaxf(ra[r].z, 0.f); ra[r].w = fmaxf(ra[r].w, 0.f);
            }
        }
#pragma unroll
        for (int r = 0; r < 2; r++) {
            int i = tid + r * 128;
            if (BT) {
                int n = i >> 2, kq = (i & 3) * 4;
                rb[r] = *(const float4*)(W + (size_t)(n0 + n) * ldw + k0 + kq);
            } else {
                int k = i >> 4, nq = (i & 15) * 4;
                rb[r] = *(const float4*)(W + (size_t)(k0 + k) * ldw + n0 + nq);
            }
        }
    };
    auto stS = [&](int buf) {
#pragma unroll
        for (int r = 0; r < 2; r++) {
            int i = tid + r * 128;
            int m = i >> 2, kq = (i & 3) * 4;
            As[buf][kq + 0][m] = ra[r].x; As[buf][kq + 1][m] = ra[r].y;
            As[buf][kq + 2][m] = ra[r].z; As[buf][kq + 3][m] = ra[r].w;
        }
#pragma unroll
        for (int r = 0; r < 2; r++) {
            int i = tid + r * 128;
            if (BT) {
                int n = i >> 2, kq = (i & 3) * 4;
                Bs[buf][kq + 0][n] = rb[r].x; Bs[buf][kq + 1][n] = rb[r].y;
                Bs[buf][kq + 2][n] = rb[r].z; Bs[buf][kq + 3][n] = rb[r].w;
            } else {
                int k = i >> 4, nq = (i & 15) * 4;
                *(float4*)&Bs[buf][k][nq] = rb[r];
            }
        }
    };

    ldG(0);
    stS(0);
    __syncthreads();
    const int ntile = K / 16;
#pragma unroll 1
    for (int t = 0; t < ntile; t++) {
        const int cur = t & 1;
        if (t + 1 < ntile) ldG((t + 1) * 16);
#pragma unroll
        for (int kk = 0; kk < 16; kk++) {
            float4 a0 = *(const float4*)&As[cur][kk][mt];
            float4 a1 = *(const float4*)&As[cur][kk][mt + 4];
            float4 bv = *(const float4*)&Bs[cur][kk][nt];
            u64 pb0 = *(u64*)&bv.x, pb1 = *(u64*)&bv.z;
            float av[8] = {a0.x, a0.y, a0.z, a0.w, a1.x, a1.y, a1.z, a1.w};
#pragma unroll
            for (int i = 0; i < 8; i++) {
                u64 pa;
                PACK_BCAST(pa, av[i]);
                FMA_F32X2(acc2[i][0], pa, pb0, acc2[i][0]);
                FMA_F32X2(acc2[i][1], pa, pb1, acc2[i][1]);
            }
        }
        if (t + 1 < ntile) stS(cur ^ 1);
        __syncthreads();
    }

#pragma unroll
    for (int i = 0; i < 8; i++) {
        float2 f0 = *(float2*)&acc2[i][0];
        float2 f1 = *(float2*)&acc2[i][1];
        *(float4*)(C + (size_t)(mt + i) * ldc + n0 + nt) =
            make_float4(f0.x, f0.y, f1.x, f1.y);
    }
}

// GRU gate GEMMs: grid (24 n-tiles, 2 k-splits, 2 which) = 96 blocks
__global__ void __launch_bounds__(128) k_gru(const int* __restrict__ idx,
        const float* __restrict__ emb, const float* __restrict__ h0,
        const float* __restrict__ W_ih, const float* __restrict__ W_hh) {
    const int ks = blockIdx.y;
    const int koff = ks * 256;
    if (blockIdx.z == 0)
        gemmN64<true, true>(emb + koff, EE, W_ih + koff, EE,
                            g_gi + ks * BB * 3 * HH, 3 * HH, 256,
                            blockIdx.x * 64, idx);
    else
        gemmN64<true, false>(h0 + koff, HH, W_hh + koff, HH,
                             g_gh + ks * BB * 3 * HH, 3 * HH, 256,
                             blockIdx.x * 64, nullptr);
}

// u partials: grid (8 n-tiles, 4 k-splits) = 32 blocks
__global__ void __launch_bounds__(128) k_u(const float* __restrict__ Wa) {
    const int ks = blockIdx.y;
    gemmN64<false, false>(g_A + ks * 128, 1024,
                          Wa + (size_t)(ks * 128) * HH, HH,
                          g_upart + ks * BB * HH, HH,
                          128, blockIdx.x * 64, nullptr);
}

// ---------------- GRU gate combine (sums k-split partials, adds biases) ----
__global__ void k_gates(const float* __restrict__ h0,
                        const float* __restrict__ b_ih, const float* __restrict__ b_hh,
                        float* __restrict__ out_hidden) {
    int i = blockIdx.x * 256 + threadIdx.x;
    int b = i >> 9, h = i & 511;
    const int P = BB * 3 * HH;
    int base = b * 1536 + h;
    float gir = g_gi[base]          + g_gi[P + base]          + b_ih[h];
    float ghr = g_gh[base]          + g_gh[P + base]          + b_hh[h];
    float giz = g_gi[base + 512]    + g_gi[P + base + 512]    + b_ih[512 + h];
    float ghz = g_gh[base + 512]    + g_gh[P + base + 512]    + b_hh[512 + h];
    float gin = g_gi[base + 1024]   + g_gi[P + base + 1024]   + b_ih[1024 + h];
    float ghn = g_gh[base + 1024]   + g_gh[P + base + 1024]   + b_hh[1024 + h];
    float r = 1.f / (1.f + __expf(-(gir + ghr)));
    float z = 1.f / (1.f + __expf(-(giz + ghz)));
    float n = tanhf(gin + r * ghn);
    float hv = (1.f - z) * n + z * h0[b * HH + h];
    g_A[b * 1024 + h] = hv;
    out_hidden[b * HH + h] = hv;
}

// ---------------- classifier tile body: 64x128, 128 thr, 8x8 micro --------
__device__ __forceinline__ void cls8(float* __restrict__ smbase,
                                     const float* __restrict__ A,
                                     const float* __restrict__ W,
                                     float* __restrict__ C, int n0, int ntile) {
    float (*As)[16][68]  = (float(*)[16][68])smbase;             // 2176 floats
    float (*Bs)[16][132] = (float(*)[16][132])(smbase + 2176);   // 4224 floats
    const int tid = threadIdx.x;
    const int mt = (tid >> 4) * 8;   // 0..56
    const int nt = (tid & 15) * 8;   // 0..120

    u64 acc2[8][4];
#pragma unroll
    for (int i = 0; i < 8; i++)
#pragma unroll
        for (int j = 0; j < 4; j++) acc2[i][j] = 0ull;

    float4 ra[2], rb[4];
    auto ldG = [&](int k0) {
#pragma unroll
        for (int r = 0; r < 2; r++) {
            int i = tid + r * 128;
            int m = i >> 2, kq = (i & 3) * 4;
            ra[r] = *(const float4*)(A + (size_t)m * 1024 + k0 + kq);
        }
#pragma unroll
        for (int r = 0; r < 4; r++) {
            int i = tid + r * 128;
            int n = i >> 2, kq = (i & 3) * 4;
            rb[r] = *(const float4*)(W + (size_t)(n0 + n) * 1024 + k0 + kq);
        }
    };
    auto stS = [&](int buf) {
#pragma unroll
        for (int r = 0; r < 2; r++) {
            int i = tid + r * 128;
            int m = i >> 2, kq = (i & 3) * 4;
            As[buf][kq + 0][m] = ra[r].x; As[buf][kq + 1][m] = ra[r].y;
            As[buf][kq + 2][m] = ra[r].z; As[buf][kq + 3][m] = ra[r].w;
        }
#pragma unroll
        for (int r = 0; r < 4; r++) {
            int i = tid + r * 128;
            int n = i >> 2, kq = (i & 3) * 4;
            Bs[buf][kq + 0][n] = rb[r].x; Bs[buf][kq + 1][n] = rb[r].y;
            Bs[buf][kq + 2][n] = rb[r].z; Bs[buf][kq + 3][n] = rb[r].w;
        }
    };

    ldG(0);
    stS(0);
    __syncthreads();
#pragma unroll 1
    for (int t = 0; t < ntile; t++) {
        const int cur = t & 1;
        if (t + 1 < ntile) ldG((t + 1) * 16);
#pragma unroll
        for (int kk = 0; kk < 16; kk++) {
            float4 a0 = *(const float4*)&As[cur][kk][mt];
            float4 a1 = *(const float4*)&As[cur][kk][mt + 4];
            const u64* bp = (const u64*)&Bs[cur][kk][nt];
            u64 pb0 = bp[0], pb1 = bp[1], pb2 = bp[2], pb3 = bp[3];
            float av[8] = {a0.x, a0.y, a0.z, a0.w, a1.x, a1.y, a1.z, a1.w};
#pragma unroll
            for (int i = 0; i < 8; i++) {
                u64 pa;
                PACK_BCAST(pa, av[i]);
                FMA_F32X2(acc2[i][0], pa, pb0, acc2[i][0]);
                FMA_F32X2(acc2[i][1], pa, pb1, acc2[i][1]);
                FMA_F32X2(acc2[i][2], pa, pb2, acc2[i][2]);
                FMA_F32X2(acc2[i][3], pa, pb3, acc2[i][3]);
            }
        }
        if (t + 1 < ntile) stS(cur ^ 1);
        __syncthreads();
    }

#pragma unroll
    for (int i = 0; i < 8; i++) {
        float o[8];
#pragma unroll
        for (int jp = 0; jp < 4; jp++) {
            float2 f = *reinterpret_cast<float2*>(&acc2[i][jp]);
            o[2 * jp] = f.x; o[2 * jp + 1] = f.y;
        }
        size_t base = (size_t)(mt + i) * VV + n0 + nt;
        *(float4*)(C + base)     = make_float4(o[0], o[1], o[2], o[3]);
        *(float4*)(C + base + 4) = make_float4(o[4], o[5], o[6], o[7]);
    }
}

// ---------------- attention body, 128 thr, warp-per-row, 2-deep prefetch ---
__device__ __forceinline__ void attn_body128(float* __restrict__ sm,
                                             const float* __restrict__ enc, int abid) {
    const int sp = abid & (NSPLIT - 1);
    const int b = abid >> 5;                          // NSPLIT = 32
    const int t = threadIdx.x;
    const int wid = t >> 5, lane = t & 31;
    float* su = sm;                                   // 512
    float (*sctx)[HH] = (float(*)[HH])(sm + 512);     // 4*512
    float* sml = sm + 512 + 4 * HH;                   // 8

    const float* up = g_upart + b * HH;
#pragma unroll
    for (int r = 0; r < 4; r++) {
        int h = t + r * 128;
        su[h] = up[h] + up[BB * HH + h] + up[2 * BB * HH + h] + up[3 * BB * HH + h];
    }
    __syncthreads();

    float4 u4[4];
#pragma unroll
    for (int j = 0; j < 4; j++) u4[j] = ((const float4*)su)[lane + 32 * j];

    float m = -INFINITY, l = 0.f;
    float4 acc[4];
#pragma unroll
    for (int j = 0; j < 4; j++) acc[j] = make_float4(0.f, 0.f, 0.f, 0.f);

    const int s0 = sp * SPLIT_S;                      // SPLIT_S = 64, 16 iters/warp
    float4 v0[4], v1[4];
    {
        const float4* r0 = (const float4*)(enc + ((size_t)(s0 + wid) * BB + b) * HH);
        const float4* r1 = (const float4*)(enc + ((size_t)(s0 + wid + 4) * BB + b) * HH);
#pragma unroll
        for (int j = 0; j < 4; j++) { v0[j] = r0[lane + 32 * j]; v1[j] = r1[lane + 32 * j]; }
    }

#pragma unroll 1
    for (int it = 0; it < SPLIT_S / 4; it++) {        // 16 iterations
        float4 v2[4];
        if (it + 2 < SPLIT_S / 4) {
            const float4* rn = (const float4*)(enc + ((size_t)(s0 + wid + (it + 2) * 4) * BB + b) * HH);
#pragma unroll
            for (int j = 0; j < 4; j++) v2[j] = rn[lane + 32 * j];
        } else {
#pragma unroll
            for (int j = 0; j < 4; j++) v2[j] = make_float4(0.f, 0.f, 0.f, 0.f);
        }
        float p = 0.f;
#pragma unroll
        for (int j = 0; j < 4; j++)
            p += v0[j].x * u4[j].x + v0[j].y * u4[j].y + v0[j].z * u4[j].z + v0[j].w * u4[j].w;
#pragma unroll
        for (int o = 16; o; o >>= 1) p += __shfl_xor_sync(0xffffffffu, p, o);

        float nm = fmaxf(m, p);
        float sc = __expf(m - nm);
        float w = __expf(p - nm);
        l = l * sc + w;
#pragma unroll
        for (int j = 0; j < 4; j++) {
            acc[j].x = acc[j].x * sc + w * v0[j].x;
            acc[j].y = acc[j].y * sc + w * v0[j].y;
            acc[j].z = acc[j].z * sc + w * v0[j].z;
            acc[j].w = acc[j].w * sc + w * v0[j].w;
        }
        m = nm;
#pragma unroll
        for (int j = 0; j < 4; j++) { v0[j] = v1[j]; v1[j] = v2[j]; }
    }

#pragma unroll
    for (int j = 0; j < 4; j++) ((float4*)sctx[wid])[lane + 32 * j] = acc[j];
    if (lane == 0) { sml[wid * 2] = m; sml[wid * 2 + 1] = l; }
    __syncthreads();

    float M = -INFINITY;
#pragma unroll
    for (int w = 0; w < 4; w++) M = fmaxf(M, sml[w * 2]);
    float L = 0.f, c[4] = {0.f, 0.f, 0.f, 0.f};
#pragma unroll
    for (int w = 0; w < 4; w++) {
        float e = __expf(sml[w * 2] - M);
        L += e * sml[w * 2 + 1];
#pragma unroll
        for (int r = 0; r < 4; r++) c[r] += e * sctx[w][t + r * 128];
    }
    size_t base = ((size_t)sp * BB + b) * HH;
#pragma unroll
    for (int r = 0; r < 4; r++) g_pctx[base + t + r * 128] = c[r];
    if (t == 0) {
        g_pml[(sp * BB + b) * 2] = M;
        g_pml[(sp * BB + b) * 2 + 1] = L;
    }
}

// ---------------- mega: 500 k-split cls_h whales FIRST, then attention -----
__global__ void __launch_bounds__(128) k_mega(const float* __restrict__ enc,
                                              const float* __restrict__ W_cls,
                                              float* __restrict__ out) {
    __shared__ __align__(16) float sm[6400];   // 25.6 KB union
    if (blockIdx.x < NCLSH) {
        const int ks = blockIdx.x & 1;          // k-half 0 -> out, 1 -> g_ph
        const int tile = blockIdx.x >> 1;       // 0..249
        const int koff = ks * 256;
        float* C = ks ? g_ph : out;
        cls8(sm, g_A + koff, W_cls + koff, C, tile * 128, 16);   // K = 256
    } else {
        attn_body128(sm, enc, blockIdx.x - NCLSH);
    }
}

// ---------------- ctx-half of classifier: k-split x2, 4 blocks/SM ----------
__global__ void __launch_bounds__(128, 4) k_cls_ctx(const float* __restrict__ W_cls) {
    __shared__ __align__(16) float sm[6400];
    const int ks = blockIdx.y;
    const int koff = 512 + ks * 256;
    float* C = ks ? g_p1 : g_p0;
    cls8(sm, g_A + koff, W_cls + koff, C, blockIdx.x * 128, 16);   // K = 256
}

// ---------------- combine splits (32) ----------------
__global__ void k_comb() {
    int b = blockIdx.x, t = threadIdx.x;      // 256 threads
    __shared__ float sm[NSPLIT], sl[NSPLIT];
    if (t < NSPLIT) {
        sm[t] = g_pml[(t * BB + b) * 2];
        sl[t] = g_pml[(t * BB + b) * 2 + 1];
    }
    __syncthreads();
    float M = -INFINITY;
#pragma unroll
    for (int i = 0; i < NSPLIT; i++) M = fmaxf(M, sm[i]);
    float L = 0.f;
#pragma unroll
    for (int i = 0; i < NSPLIT; i++) L += sl[i] * __expf(sm[i] - M);
    float inv = 1.f / L;
    float o0 = 0.f, o1 = 0.f;
#pragma unroll 8
    for (int i = 0; i < NSPLIT; i++) {
        float w = __expf(sm[i] - M);
        size_t base = ((size_t)i * BB + b) * HH;
        o0 += w * g_pctx[base + t];
        o1 += w * g_pctx[base + t + 256];
    }
    g_A[b * 1024 + 512 + t] = o0 * inv;
    g_A[b * 1024 + 512 + t + 256] = o1 * inv;
}

// ---------------- fused log-softmax over (out + ph + p0 + p1 + bias) --------
__global__ void k_lsefix(float* __restrict__ out, const float* __restrict__ b_cls) {
    const int b = blockIdx.x, t = threadIdx.x;   // 1024 threads
    float4* rowO = (float4*)(out + (size_t)b * VV);
    const float4* rowH  = (const float4*)(g_ph + (size_t)b * VV);
    const float4* rowP0 = (const float4*)(g_p0 + (size_t)b * VV);
    const float4* rowP1 = (const float4*)(g_p1 + (size_t)b * VV);
    const float4* bias4 = (const float4*)b_cls;
    __shared__ float red[32];
    __shared__ float sM, sL;
    const int lane = t & 31, wid = t >> 5;

    float mx = -INFINITY;
    for (int i = t; i < VV / 4; i += 1024) {
        float4 v = rowO[i], hh = rowH[i], a = rowP0[i], c4 = rowP1[i], bb = bias4[i];
        float x = v.x + hh.x + a.x + c4.x + bb.x;
        float y = v.y + hh.y + a.y + c4.y + bb.y;
        float z = v.z + hh.z + a.z + c4.z + bb.z;
        float w = v.w + hh.w + a.w + c4.w + bb.w;
        mx = fmaxf(mx, fmaxf(fmaxf(x, y), fmaxf(z, w)));
    }
#pragma unroll
    for (int o = 16; o; o >>= 1) mx = fmaxf(mx, __shfl_xor_sync(0xffffffffu, mx, o));
    if (lane == 0) red[wid] = mx;
    __syncthreads();
    if (t < 32) {
        float q = red[t];
#pragma unroll
        for (int o = 16; o; o >>= 1) q = fmaxf(q, __shfl_xor_sync(0xffffffffu, q, o));
        if (t == 0) sM = q;
    }
    __syncthreads();
    const float M = sM;

    float s = 0.f;
    for (int i = t; i < VV / 4; i += 1024) {
        float4 v = rowO[i], hh = rowH[i], a = rowP0[i], c4 = rowP1[i], bb = bias4[i];
        s += __expf(v.x + hh.x + a.x + c4.x + bb.x - M)
           + __expf(v.y + hh.y + a.y + c4.y + bb.y - M)
           + __expf(v.z + hh.z + a.z + c4.z + bb.z - M)
           + __expf(v.w + hh.w + a.w + c4.w + bb.w - M);
    }
#pragma unroll
    for (int o = 16; o; o >>= 1) s += __shfl_xor_sync(0xffffffffu, s, o);
    if (lane == 0) red[wid] = s;
    __syncthreads();
    if (t < 32) {
        float q = red[t];
#pragma unroll
        for (int o = 16; o; o >>= 1) q += __shfl_xor_sync(0xffffffffu, q, o);
        if (t == 0) sL = q;
    }
    __syncthreads();
    const float c = M + logf(sL);

    for (int i = t; i < VV / 4; i += 1024) {
        float4 v = rowO[i], hh = rowH[i], a = rowP0[i], c4 = rowP1[i], bb = bias4[i];
        v.x = v.x + hh.x + a.x + c4.x + bb.x - c;
        v.y = v.y + hh.y + a.y + c4.y + bb.y - c;
        v.z = v.z + hh.z + a.z + c4.z + bb.z - c;
        v.w = v.w + hh.w + a.w + c4.w + bb.w - c;
        rowO[i] = v;
    }
}

// ---------------- launch ----------------
extern "C" void kernel_launch(void* const* d_in, const int* in_sizes, int n_in,
                              void* d_out, int out_size) {
    const int*   dec_inputs = (const int*)d_in[0];
    const float* enc        = (const float*)d_in[1];
    const float* h0         = (const float*)d_in[2];
    const float* emb        = (const float*)d_in[3];
    const float* W_ih       = (const float*)d_in[4];
    const float* W_hh       = (const float*)d_in[5];
    const float* b_ih       = (const float*)d_in[6];
    const float* b_hh       = (const float*)d_in[7];
    const float* W_attn     = (const float*)d_in[8];
    const float* b_attn     = (const float*)d_in[9];   // cancels in softmax
    const float* W_cls      = (const float*)d_in[10];
    const float* b_cls      = (const float*)d_in[11];
    (void)b_attn; (void)in_sizes; (void)n_in; (void)out_size;

    float* out        = (float*)d_out;
    float* out_hidden = (float*)d_out + (size_t)BB * VV;

    k_gru<<<dim3(24, 2, 2), 128>>>(dec_inputs, emb, h0, W_ih, W_hh);
    k_gates<<<BB * HH / 256, 256>>>(h0, b_ih, b_hh, out_hidden);
    k_u<<<dim3(8, 4), 128>>>(W_attn);
    k_mega<<<NCLSH + NATTN, 128>>>(enc, W_cls, out);
    k_comb<<<BB, 256>>>();
    k_cls_ctx<<<dim3(NCLS_TILES, 2), 128>>>(W_cls);
    k_lsefix<<<BB, 1024>>>(out, b_cls);
}

// round 14
// speedup vs baseline: 1.3545x; 1.3545x over previous
#include <cuda_runtime.h>
#include <math.h>

#define BB 64
#define HH 512
#define EE 512
#define SS 2048
#define VV 32000
#define NSPLIT 32
#define SPLIT_S (SS / NSPLIT)      // 64
#define NCLS_TILES 250             // 32000 / 128
#define NATTN (NSPLIT * BB)        // 2048

#define FMA_F32X2(d, a, b, c) \
    asm("fma.rn.f32x2 %0, %1, %2, %3;" : "=l"(d) : "l"(a), "l"(b), "l"(c))
#define PACK_BCAST(d, f) \
    asm("mov.b64 %0, {%1, %1};" : "=l"(d) : "r"(__float_as_uint(f)))
#define MMA_TF32(d0, d1, d2, d3, a0, a1, a2, a3, b0, b1) \
    asm volatile("mma.sync.aligned.m16n8k8.row.col.f32.tf32.tf32.f32 " \
                 "{%0,%1,%2,%3}, {%4,%5,%6,%7}, {%8,%9}, {%0,%1,%2,%3};" \
                 : "+f"(d0), "+f"(d1), "+f"(d2), "+f"(d3) \
                 : "r"(a0), "r"(a1), "r"(a2), "r"(a3), "r"(b0), "r"(b1))

typedef unsigned long long u64;
typedef unsigned int u32;

__device__ __forceinline__ u32 f2tf(float f) {
    u32 r;
    asm("cvt.rna.tf32.f32 %0, %1;" : "=r"(r) : "f"(f));
    return r;
}

// ---------------- scratch ----------------
__device__ float g_gi[2 * BB * 3 * HH];     // 2 k-split partials
__device__ float g_gh[2 * BB * 3 * HH];
__device__ float g_A[BB * 2 * HH];          // [h_new | context]
__device__ float g_upart[4 * BB * HH];      // k-split partials of u
__device__ float g_pctx[(size_t)NSPLIT * BB * HH];
__device__ float g_pml[NSPLIT * BB * 2];
__device__ float g_p0[(size_t)BB * VV];     // ctx-half logit partial

// ---------------- gemmN64: 64M x 64N tile, 128 thr, f32x2 ------------------
// BT=true : W[n][k].  BT=false: W[k][n].  GATHER: A row = relu(emb[idx[m]]).
template<bool BT, bool GATHER>
__device__ __forceinline__ void gemmN64(const float* __restrict__ A, int lda,
                                        const float* __restrict__ W, int ldw,
                                        float* __restrict__ C, int ldc,
                                        int K, int n0, const int* __restrict__ gidx) {
    __shared__ float As[2][16][68];
    __shared__ float Bs[2][16][68];
    const int tid = threadIdx.x;
    const int mt = (tid >> 4) * 8;   // 0..56
    const int nt = (tid & 15) * 4;   // 0..60

    u64 acc2[8][2];
#pragma unroll
    for (int i = 0; i < 8; i++) { acc2[i][0] = 0ull; acc2[i][1] = 0ull; }

    float4 ra[2], rb[2];
    auto ldG = [&](int k0) {
#pragma unroll
        for (int r = 0; r < 2; r++) {
            int i = tid + r * 128;
            int m = i >> 2, kq = (i & 3) * 4;
            int row = GATHER ? gidx[m] : m;
            ra[r] = *(const float4*)(A + (size_t)row * lda + k0 + kq);
            if (GATHER) {
                ra[r].x = fmaxf(ra[r].x, 0.f); ra[r].y = fmaxf(ra[r].y, 0.f);
                ra[r].z = fmaxf(ra[r].z, 0.f); ra[r].w = fmaxf(ra[r].w, 0.f);
            }
        }
#pragma unroll
        for (int r = 0; r < 2; r++) {
            int i = tid + r * 128;
            if (BT) {
                int n = i >> 2, kq = (i & 3) * 4;
                rb[r] = *(const float4*)(W + (size_t)(n0 + n) * ldw + k0 + kq);
            } else {
                int k = i >> 4, nq = (i & 15) * 4;
                rb[r] = *(const float4*)(W + (size_t)(k0 + k) * ldw + n0 + nq);
            }
        }
    };
    auto stS = [&](int buf) {
#pragma unroll
        for (int r = 0; r < 2; r++) {
            int i = tid + r * 128;
            int m = i >> 2, kq = (i & 3) * 4;
            As[buf][kq + 0][m] = ra[r].x; As[buf][kq + 1][m] = ra[r].y;
            As[buf][kq + 2][m] = ra[r].z; As[buf][kq + 3][m] = ra[r].w;
        }
#pragma unroll
        for (int r = 0; r < 2; r++) {
            int i = tid + r * 128;
            if (BT) {
                int n = i >> 2, kq = (i & 3) * 4;
                Bs[buf][kq + 0][n] = rb[r].x; Bs[buf][kq + 1][n] = rb[r].y;
                Bs[buf][kq + 2][n] = rb[r].z; Bs[buf][kq + 3][n] = rb[r].w;
            } else {
                int k = i >> 4, nq = (i & 15) * 4;
                *(float4*)&Bs[buf][k][nq] = rb[r];
            }
        }
    };

    ldG(0);
    stS(0);
    __syncthreads();
    const int ntile = K / 16;
#pragma unroll 1
    for (int t = 0; t < ntile; t++) {
        const int cur = t & 1;
        if (t + 1 < ntile) ldG((t + 1) * 16);
#pragma unroll
        for (int kk = 0; kk < 16; kk++) {
            float4 a0 = *(const float4*)&As[cur][kk][mt];
            float4 a1 = *(const float4*)&As[cur][kk][mt + 4];
            float4 bv = *(const float4*)&Bs[cur][kk][nt];
            u64 pb0 = *(u64*)&bv.x, pb1 = *(u64*)&bv.z;
            float av[8] = {a0.x, a0.y, a0.z, a0.w, a1.x, a1.y, a1.z, a1.w};
#pragma unroll
            for (int i = 0; i < 8; i++) {
                u64 pa;
                PACK_BCAST(pa, av[i]);
                FMA_F32X2(acc2[i][0], pa, pb0, acc2[i][0]);
                FMA_F32X2(acc2[i][1], pa, pb1, acc2[i][1]);
            }
        }
        if (t + 1 < ntile) stS(cur ^ 1);
        __syncthreads();
    }

#pragma unroll
    for (int i = 0; i < 8; i++) {
        float2 f0 = *(float2*)&acc2[i][0];
        float2 f1 = *(float2*)&acc2[i][1];
        *(float4*)(C + (size_t)(mt + i) * ldc + n0 + nt) =
            make_float4(f0.x, f0.y, f1.x, f1.y);
    }
}

// GRU gate GEMMs: grid (24 n-tiles, 2 k-splits, 2 which) = 96 blocks
__global__ void __launch_bounds__(128) k_gru(const int* __restrict__ idx,
        const float* __restrict__ emb, const float* __restrict__ h0,
        const float* __restrict__ W_ih, const float* __restrict__ W_hh) {
    const int ks = blockIdx.y;
    const int koff = ks * 256;
    if (blockIdx.z == 0)
        gemmN64<true, true>(emb + koff, EE, W_ih + koff, EE,
                            g_gi + ks * BB * 3 * HH, 3 * HH, 256,
                            blockIdx.x * 64, idx);
    else
        gemmN64<true, false>(h0 + koff, HH, W_hh + koff, HH,
                             g_gh + ks * BB * 3 * HH, 3 * HH, 256,
                             blockIdx.x * 64, nullptr);
}

// u partials: grid (8 n-tiles, 4 k-splits) = 32 blocks
__global__ void __launch_bounds__(128) k_u(const float* __restrict__ Wa) {
    const int ks = blockIdx.y;
    gemmN64<false, false>(g_A + ks * 128, 1024,
                          Wa + (size_t)(ks * 128) * HH, HH,
                          g_upart + ks * BB * HH, HH,
                          128, blockIdx.x * 64, nullptr);
}

// ---------------- GRU gate combine (sums k-split partials, adds biases) ----
__global__ void k_gates(const float* __restrict__ h0,
                        const float* __restrict__ b_ih, const float* __restrict__ b_hh,
                        float* __restrict__ out_hidden) {
    int i = blockIdx.x * 256 + threadIdx.x;
    int b = i >> 9, h = i & 511;
    const int P = BB * 3 * HH;
    int base = b * 1536 + h;
    float gir = g_gi[base]          + g_gi[P + base]          + b_ih[h];
    float ghr = g_gh[base]          + g_gh[P + base]          + b_hh[h];
    float giz = g_gi[base + 512]    + g_gi[P + base + 512]    + b_ih[512 + h];
    float ghz = g_gh[base + 512]    + g_gh[P + base + 512]    + b_hh[512 + h];
    float gin = g_gi[base + 1024]   + g_gi[P + base + 1024]   + b_ih[1024 + h];
    float ghn = g_gh[base + 1024]   + g_gh[P + base + 1024]   + b_hh[1024 + h];
    float r = 1.f / (1.f + __expf(-(gir + ghr)));
    float z = 1.f / (1.f + __expf(-(giz + ghz)));
    float n = tanhf(gin + r * ghn);
    float hv = (1.f - z) * n + z * h0[b * HH + h];
    g_A[b * 1024 + h] = hv;
    out_hidden[b * HH + h] = hv;
}

// ---------------- classifier tile, tf32 MMA: 64x128, 128 thr ---------------
// Warp quadrant (wid>>1, wid&1): M rows [wm,wm+32), N cols [wn,wn+64).
// Per k8: 2 A-frags, 8 B-frags, 16 HMMA. Accum 64 fp32/lane.
__device__ __forceinline__ void cls_tf32(float* __restrict__ smbase,
                                         const float* __restrict__ A,
                                         const float* __restrict__ W,
                                         float* __restrict__ C, int n0, int ntile) {
    float (*As)[16][68]  = (float(*)[16][68])smbase;             // [k][m]
    float (*Bs)[16][132] = (float(*)[16][132])(smbase + 2176);   // [k][n]
    const int tid = threadIdx.x;
    const int wid = tid >> 5, lane = tid & 31;
    const int gid = lane >> 2, tig = lane & 3;
    const int wm = (wid >> 1) * 32;   // 0 or 32
    const int wn = (wid & 1) * 64;    // 0 or 64

    float d[2][8][4];
#pragma unroll
    for (int ms = 0; ms < 2; ms++)
#pragma unroll
        for (int nc = 0; nc < 8; nc++)
#pragma unroll
            for (int j = 0; j < 4; j++) d[ms][nc][j] = 0.f;

    float4 ra[2], rb[4];
    auto ldG = [&](int k0) {
#pragma unroll
        for (int r = 0; r < 2; r++) {
            int i = tid + r * 128;
            int m = i >> 2, kq = (i & 3) * 4;
            ra[r] = *(const float4*)(A + (size_t)m * 1024 + k0 + kq);
        }
#pragma unroll
        for (int r = 0; r < 4; r++) {
            int i = tid + r * 128;
            int n = i >> 2, kq = (i & 3) * 4;
            rb[r] = *(const float4*)(W + (size_t)(n0 + n) * 1024 + k0 + kq);
        }
    };
    auto stS = [&](int buf) {
#pragma unroll
        for (int r = 0; r < 2; r++) {
            int i = tid + r * 128;
            int m = i >> 2, kq = (i & 3) * 4;
            As[buf][kq + 0][m] = ra[r].x; As[buf][kq + 1][m] = ra[r].y;
            As[buf][kq + 2][m] = ra[r].z; As[buf][kq + 3][m] = ra[r].w;
        }
#pragma unroll
        for (int r = 0; r < 4; r++) {
            int i = tid + r * 128;
            int n = i >> 2, kq = (i & 3) * 4;
            Bs[buf][kq + 0][n] = rb[r].x; Bs[buf][kq + 1][n] = rb[r].y;
            Bs[buf][kq + 2][n] = rb[r].z; Bs[buf][kq + 3][n] = rb[r].w;
        }
    };

    ldG(0);
    stS(0);
    __syncthreads();
#pragma unroll 1
    for (int t = 0; t < ntile; t++) {
        const int cur = t & 1;
        if (t + 1 < ntile) ldG((t + 1) * 16);
#pragma unroll
        for (int k8 = 0; k8 < 16; k8 += 8) {
            // A fragments: a0(gid,tig) a1(gid+8,tig) a2(gid,tig+4) a3(gid+8,tig+4)
            u32 a[2][4];
#pragma unroll
            for (int ms = 0; ms < 2; ms++) {
                int m0 = wm + ms * 16;
                a[ms][0] = f2tf(As[cur][k8 + tig][m0 + gid]);
                a[ms][1] = f2tf(As[cur][k8 + tig][m0 + gid + 8]);
                a[ms][2] = f2tf(As[cur][k8 + tig + 4][m0 + gid]);
                a[ms][3] = f2tf(As[cur][k8 + tig + 4][m0 + gid + 8]);
            }
#pragma unroll
            for (int nc = 0; nc < 8; nc++) {
                int nb = wn + nc * 8;
                u32 b0 = f2tf(Bs[cur][k8 + tig][nb + gid]);
                u32 b1 = f2tf(Bs[cur][k8 + tig + 4][nb + gid]);
                MMA_TF32(d[0][nc][0], d[0][nc][1], d[0][nc][2], d[0][nc][3],
                         a[0][0], a[0][1], a[0][2], a[0][3], b0, b1);
                MMA_TF32(d[1][nc][0], d[1][nc][1], d[1][nc][2], d[1][nc][3],
                         a[1][0], a[1][1], a[1][2], a[1][3], b0, b1);
            }
        }
        if (t + 1 < ntile) stS(cur ^ 1);
        __syncthreads();
    }

    // epilogue: d0,d1 -> row gid, cols tig*2,tig*2+1 ; d2,d3 -> row gid+8
#pragma unroll
    for (int ms = 0; ms < 2; ms++) {
        int m0 = wm + ms * 16 + gid;
#pragma unroll
        for (int nc = 0; nc < 8; nc++) {
            int n = n0 + wn + nc * 8 + tig * 2;
            *(float2*)(C + (size_t)m0 * VV + n) =
                make_float2(d[ms][nc][0], d[ms][nc][1]);
            *(float2*)(C + (size_t)(m0 + 8) * VV + n) =
                make_float2(d[ms][nc][2], d[ms][nc][3]);
        }
    }
}

// ---------------- attention body, 128 thr, warp-per-row, 2-deep prefetch ---
__device__ __forceinline__ void attn_body128(float* __restrict__ sm,
                                             const float* __restrict__ enc, int abid) {
    const int sp = abid & (NSPLIT - 1);
    const int b = abid >> 5;                          // NSPLIT = 32
    const int t = threadIdx.x;
    const int wid = t >> 5, lane = t & 31;
    float* su = sm;                                   // 512
    float (*sctx)[HH] = (float(*)[HH])(sm + 512);     // 4*512
    float* sml = sm + 512 + 4 * HH;                   // 8

    const float* up = g_upart + b * HH;
#pragma unroll
    for (int r = 0; r < 4; r++) {
        int h = t + r * 128;
        su[h] = up[h] + up[BB * HH + h] + up[2 * BB * HH + h] + up[3 * BB * HH + h];
    }
    __syncthreads();

    float4 u4[4];
#pragma unroll
    for (int j = 0; j < 4; j++) u4[j] = ((const float4*)su)[lane + 32 * j];

    float m = -INFINITY, l = 0.f;
    float4 acc[4];
#pragma unroll
    for (int j = 0; j < 4; j++) acc[j] = make_float4(0.f, 0.f, 0.f, 0.f);

    const int s0 = sp * SPLIT_S;                      // SPLIT_S = 64, 16 iters/warp
    float4 v0[4], v1[4];
    {
        const float4* r0 = (const float4*)(enc + ((size_t)(s0 + wid) * BB + b) * HH);
        const float4* r1 = (const float4*)(enc + ((size_t)(s0 + wid + 4) * BB + b) * HH);
#pragma unroll
        for (int j = 0; j < 4; j++) { v0[j] = r0[lane + 32 * j]; v1[j] = r1[lane + 32 * j]; }
    }

#pragma unroll 1
    for (int it = 0; it < SPLIT_S / 4; it++) {        // 16 iterations
        float4 v2[4];
        if (it + 2 < SPLIT_S / 4) {
            const float4* rn = (const float4*)(enc + ((size_t)(s0 + wid + (it + 2) * 4) * BB + b) * HH);
#pragma unroll
            for (int j = 0; j < 4; j++) v2[j] = rn[lane + 32 * j];
        } else {
#pragma unroll
            for (int j = 0; j < 4; j++) v2[j] = make_float4(0.f, 0.f, 0.f, 0.f);
        }
        float p = 0.f;
#pragma unroll
        for (int j = 0; j < 4; j++)
            p += v0[j].x * u4[j].x + v0[j].y * u4[j].y + v0[j].z * u4[j].z + v0[j].w * u4[j].w;
#pragma unroll
        for (int o = 16; o; o >>= 1) p += __shfl_xor_sync(0xffffffffu, p, o);

        float nm = fmaxf(m, p);
        float sc = __expf(m - nm);
        float w = __expf(p - nm);
        l = l * sc + w;
#pragma unroll
        for (int j = 0; j < 4; j++) {
            acc[j].x = acc[j].x * sc + w * v0[j].x;
            acc[j].y = acc[j].y * sc + w * v0[j].y;
            acc[j].z = acc[j].z * sc + w * v0[j].z;
            acc[j].w = acc[j].w * sc + w * v0[j].w;
        }
        m = nm;
#pragma unroll
        for (int j = 0; j < 4; j++) { v0[j] = v1[j]; v1[j] = v2[j]; }
    }

#pragma unroll
    for (int j = 0; j < 4; j++) ((float4*)sctx[wid])[lane + 32 * j] = acc[j];
    if (lane == 0) { sml[wid * 2] = m; sml[wid * 2 + 1] = l; }
    __syncthreads();

    float M = -INFINITY;
#pragma unroll
    for (int w = 0; w < 4; w++) M = fmaxf(M, sml[w * 2]);
    float L = 0.f, c[4] = {0.f, 0.f, 0.f, 0.f};
#pragma unroll
    for (int w = 0; w < 4; w++) {
        float e = __expf(sml[w * 2] - M);
        L += e * sml[w * 2 + 1];
#pragma unroll
        for (int r = 0; r < 4; r++) c[r] += e * sctx[w][t + r * 128];
    }
    size_t base = ((size_t)sp * BB + b) * HH;
#pragma unroll
    for (int r = 0; r < 4; r++) g_pctx[base + t + r * 128] = c[r];
    if (t == 0) {
        g_pml[(sp * BB + b) * 2] = M;
        g_pml[(sp * BB + b) * 2 + 1] = L;
    }
}

// ---------------- mega: 250 tf32 cls_h tiles FIRST, then attention ---------
__global__ void __launch_bounds__(128) k_mega(const float* __restrict__ enc,
                                              const float* __restrict__ W_cls,
                                              float* __restrict__ out) {
    __shared__ __align__(16) float sm[6400];   // 25.6 KB union
    if (blockIdx.x < NCLS_TILES)
        cls_tf32(sm, g_A, W_cls, out, blockIdx.x * 128, 32);   // K = 512 (h-half)
    else
        attn_body128(sm, enc, blockIdx.x - NCLS_TILES);
}

// ---------------- ctx-half of classifier: tf32, K=512 -> g_p0 --------------
__global__ void __launch_bounds__(128) k_cls_ctx(const float* __restrict__ W_cls) {
    __shared__ __align__(16) float sm[6400];
    cls_tf32(sm, g_A + 512, W_cls + 512, g_p0, blockIdx.x * 128, 32);
}

// ---------------- combine splits (32) ----------------
__global__ void k_comb() {
    int b = blockIdx.x, t = threadIdx.x;      // 256 threads
    __shared__ float sm[NSPLIT], sl[NSPLIT];
    if (t < NSPLIT) {
        sm[t] = g_pml[(t * BB + b) * 2];
        sl[t] = g_pml[(t * BB + b) * 2 + 1];
    }
    __syncthreads();
    float M = -INFINITY;
#pragma unroll
    for (int i = 0; i < NSPLIT; i++) M = fmaxf(M, sm[i]);
    float L = 0.f;
#pragma unroll
    for (int i = 0; i < NSPLIT; i++) L += sl[i] * __expf(sm[i] - M);
    float inv = 1.f / L;
    float o0 = 0.f, o1 = 0.f;
#pragma unroll 8
    for (int i = 0; i < NSPLIT; i++) {
        float w = __expf(sm[i] - M);
        size_t base = ((size_t)i * BB + b) * HH;
        o0 += w * g_pctx[base + t];
        o1 += w * g_pctx[base + t + 256];
    }
    g_A[b * 1024 + 512 + t] = o0 * inv;
    g_A[b * 1024 + 512 + t + 256] = o1 * inv;
}

// ---------------- fused log-softmax over (out + p0 + bias) ------------------
__global__ void k_lsefix(float* __restrict__ out, const float* __restrict__ b_cls) {
    const int b = blockIdx.x, t = threadIdx.x;   // 1024 threads
    float4* rowO = (float4*)(out + (size_t)b * VV);
    const float4* rowP0 = (const float4*)(g_p0 + (size_t)b * VV);
    const float4* bias4 = (const float4*)b_cls;
    __shared__ float red[32];
    __shared__ float sM, sL;
    const int lane = t & 31, wid = t >> 5;

    float mx = -INFINITY;
    for (int i = t; i < VV / 4; i += 1024) {
        float4 v = rowO[i], a = rowP0[i], bb = bias4[i];
        float x = v.x + a.x + bb.x, y = v.y + a.y + bb.y;
        float z = v.z + a.z + bb.z, w = v.w + a.w + bb.w;
        mx = fmaxf(mx, fmaxf(fmaxf(x, y), fmaxf(z, w)));
    }
#pragma unroll
    for (int o = 16; o; o >>= 1) mx = fmaxf(mx, __shfl_xor_sync(0xffffffffu, mx, o));
    if (lane == 0) red[wid] = mx;
    __syncthreads();
    if (t < 32) {
        float q = red[t];
#pragma unroll
        for (int o = 16; o; o >>= 1) q = fmaxf(q, __shfl_xor_sync(0xffffffffu, q, o));
        if (t == 0) sM = q;
    }
    __syncthreads();
    const float M = sM;

    float s = 0.f;
    for (int i = t; i < VV / 4; i += 1024) {
        float4 v = rowO[i], a = rowP0[i], bb = bias4[i];
        s += __expf(v.x + a.x + bb.x - M) + __expf(v.y + a.y + bb.y - M)
           + __expf(v.z + a.z + bb.z - M) + __expf(v.w + a.w + bb.w - M);
    }
#pragma unroll
    for (int o = 16; o; o >>= 1) s += __shfl_xor_sync(0xffffffffu, s, o);
    if (lane == 0) red[wid] = s;
    __syncthreads();
    if (t < 32) {
        float q = red[t];
#pragma unroll
        for (int o = 16; o; o >>= 1) q += __shfl_xor_sync(0xffffffffu, q, o);
        if (t == 0) sL = q;
    }
    __syncthreads();
    const float c = M + logf(sL);

    for (int i = t; i < VV / 4; i += 1024) {
        float4 v = rowO[i], a = rowP0[i], bb = bias4[i];
        v.x = v.x + a.x + bb.x - c;
        v.y = v.y + a.y + bb.y - c;
        v.z = v.z + a.z + bb.z - c;
        v.w = v.w + a.w + bb.w - c;
        rowO[i] = v;
    }
}

// ---------------- launch ----------------
extern "C" void kernel_launch(void* const* d_in, const int* in_sizes, int n_in,
                              void* d_out, int out_size) {
    const int*   dec_inputs = (const int*)d_in[0];
    const float* enc        = (const float*)d_in[1];
    const float* h0         = (const float*)d_in[2];
    const float* emb        = (const float*)d_in[3];
    const float* W_ih       = (const float*)d_in[4];
    const float* W_hh       = (const float*)d_in[5];
    const float* b_ih       = (const float*)d_in[6];
    const float* b_hh       = (const float*)d_in[7];
    const float* W_attn     = (const float*)d_in[8];
    const float* b_attn     = (const float*)d_in[9];   // cancels in softmax
    const float* W_cls      = (const float*)d_in[10];
    const float* b_cls      = (const float*)d_in[11];
    (void)b_attn; (void)in_sizes; (void)n_in; (void)out_size;

    float* out        = (float*)d_out;
    float* out_hidden = (float*)d_out + (size_t)BB * VV;

    k_gru<<<dim3(24, 2, 2), 128>>>(dec_inputs, emb, h0, W_ih, W_hh);
    k_gates<<<BB * HH / 256, 256>>>(h0, b_ih, b_hh, out_hidden);
    k_u<<<dim3(8, 4), 128>>>(W_attn);
    k_mega<<<NCLS_TILES + NATTN, 128>>>(enc, W_cls, out);
    k_comb<<<BB, 256>>>();
    k_cls_ctx<<<NCLS_TILES, 128>>>(W_cls);
    k_lsefix<<<BB, 1024>>>(out, b_cls);
}

// round 15
// speedup vs baseline: 1.4622x; 1.0795x over previous
#include <cuda_runtime.h>
#include <math.h>

#define BB 64
#define HH 512
#define EE 512
#define SS 2048
#define VV 32000
#define NSPLIT 32
#define SPLIT_S (SS / NSPLIT)      // 64
#define NCLS_TILES 250             // 32000 / 128
#define NATTN (NSPLIT * BB)        // 2048

#define FMA_F32X2(d, a, b, c) \
    asm("fma.rn.f32x2 %0, %1, %2, %3;" : "=l"(d) : "l"(a), "l"(b), "l"(c))
#define PACK_BCAST(d, f) \
    asm("mov.b64 %0, {%1, %1};" : "=l"(d) : "r"(__float_as_uint(f)))
#define MMA_TF32(d0, d1, d2, d3, a0, a1, a2, a3, b0, b1) \
    asm volatile("mma.sync.aligned.m16n8k8.row.col.f32.tf32.tf32.f32 " \
                 "{%0,%1,%2,%3}, {%4,%5,%6,%7}, {%8,%9}, {%0,%1,%2,%3};" \
                 : "+f"(d0), "+f"(d1), "+f"(d2), "+f"(d3) \
                 : "r"(a0), "r"(a1), "r"(a2), "r"(a3), "r"(b0), "r"(b1))

typedef unsigned long long u64;
typedef unsigned int u32;

__device__ __forceinline__ u32 f2tf(float f) {
    u32 r;
    asm("cvt.rna.tf32.f32 %0, %1;" : "=r"(r) : "f"(f));
    return r;
}

// ---------------- scratch ----------------
__device__ float g_gi[2 * BB * 3 * HH];     // 2 k-split partials
__device__ float g_gh[2 * BB * 3 * HH];
__device__ float g_A[BB * 2 * HH];          // [h_new | context]
__device__ float g_upart[4 * BB * HH];      // k-split partials of u
__device__ float g_pctx[(size_t)NSPLIT * BB * HH];
__device__ float g_pml[NSPLIT * BB * 2];
__device__ float g_p0[(size_t)BB * VV];     // ctx-half logit partial

// ---------------- gemmN64: 64M x 64N tile, 128 thr, f32x2 ------------------
// BT=true : W[n][k].  BT=false: W[k][n].  GATHER: A row = relu(emb[idx[m]]).
template<bool BT, bool GATHER>
__device__ __forceinline__ void gemmN64(const float* __restrict__ A, int lda,
                                        const float* __restrict__ W, int ldw,
                                        float* __restrict__ C, int ldc,
                                        int K, int n0, const int* __restrict__ gidx) {
    __shared__ float As[2][16][68];
    __shared__ float Bs[2][16][68];
    const int tid = threadIdx.x;
    const int mt = (tid >> 4) * 8;   // 0..56
    const int nt = (tid & 15) * 4;   // 0..60

    u64 acc2[8][2];
#pragma unroll
    for (int i = 0; i < 8; i++) { acc2[i][0] = 0ull; acc2[i][1] = 0ull; }

    float4 ra[2], rb[2];
    auto ldG = [&](int k0) {
#pragma unroll
        for (int r = 0; r < 2; r++) {
            int i = tid + r * 128;
            int m = i >> 2, kq = (i & 3) * 4;
            int row = GATHER ? gidx[m] : m;
            ra[r] = *(const float4*)(A + (size_t)row * lda + k0 + kq);
            if (GATHER) {
                ra[r].x = fmaxf(ra[r].x, 0.f); ra[r].y = fmaxf(ra[r].y, 0.f);
                ra[r].z = fmaxf(ra[r].z, 0.f); ra[r].w = fmaxf(ra[r].w, 0.f);
            }
        }
#pragma unroll
        for (int r = 0; r < 2; r++) {
            int i = tid + r * 128;
            if (BT) {
                int n = i >> 2, kq = (i & 3) * 4;
                rb[r] = *(const float4*)(W + (size_t)(n0 + n) * ldw + k0 + kq);
            } else {
                int k = i >> 4, nq = (i & 15) * 4;
                rb[r] = *(const float4*)(W + (size_t)(k0 + k) * ldw + n0 + nq);
            }
        }
    };
    auto stS = [&](int buf) {
#pragma unroll
        for (int r = 0; r < 2; r++) {
            int i = tid + r * 128;
            int m = i >> 2, kq = (i & 3) * 4;
            As[buf][kq + 0][m] = ra[r].x; As[buf][kq + 1][m] = ra[r].y;
            As[buf][kq + 2][m] = ra[r].z; As[buf][kq + 3][m] = ra[r].w;
        }
#pragma unroll
        for (int r = 0; r < 2; r++) {
            int i = tid + r * 128;
            if (BT) {
                int n = i >> 2, kq = (i & 3) * 4;
                Bs[buf][kq + 0][n] = rb[r].x; Bs[buf][kq + 1][n] = rb[r].y;
                Bs[buf][kq + 2][n] = rb[r].z; Bs[buf][kq + 3][n] = rb[r].w;
            } else {
                int k = i >> 4, nq = (i & 15) * 4;
                *(float4*)&Bs[buf][k][nq] = rb[r];
            }
        }
    };

    ldG(0);
    stS(0);
    __syncthreads();
    const int ntile = K / 16;
#pragma unroll 1
    for (int t = 0; t < ntile; t++) {
        const int cur = t & 1;
        if (t + 1 < ntile) ldG((t + 1) * 16);
#pragma unroll
        for (int kk = 0; kk < 16; kk++) {
            float4 a0 = *(const float4*)&As[cur][kk][mt];
            float4 a1 = *(const float4*)&As[cur][kk][mt + 4];
            float4 bv = *(const float4*)&Bs[cur][kk][nt];
            u64 pb0 = *(u64*)&bv.x, pb1 = *(u64*)&bv.z;
            float av[8] = {a0.x, a0.y, a0.z, a0.w, a1.x, a1.y, a1.z, a1.w};
#pragma unroll
            for (int i = 0; i < 8; i++) {
                u64 pa;
                PACK_BCAST(pa, av[i]);
                FMA_F32X2(acc2[i][0], pa, pb0, acc2[i][0]);
                FMA_F32X2(acc2[i][1], pa, pb1, acc2[i][1]);
            }
        }
        if (t + 1 < ntile) stS(cur ^ 1);
        __syncthreads();
    }

#pragma unroll
    for (int i = 0; i < 8; i++) {
        float2 f0 = *(float2*)&acc2[i][0];
        float2 f1 = *(float2*)&acc2[i][1];
        *(float4*)(C + (size_t)(mt + i) * ldc + n0 + nt) =
            make_float4(f0.x, f0.y, f1.x, f1.y);
    }
}

// GRU gate GEMMs: grid (24 n-tiles, 2 k-splits, 2 which) = 96 blocks
__global__ void __launch_bounds__(128) k_gru(const int* __restrict__ idx,
        const float* __restrict__ emb, const float* __restrict__ h0,
        const float* __restrict__ W_ih, const float* __restrict__ W_hh) {
    const int ks = blockIdx.y;
    const int koff = ks * 256;
    if (blockIdx.z == 0)
        gemmN64<true, true>(emb + koff, EE, W_ih + koff, EE,
                            g_gi + ks * BB * 3 * HH, 3 * HH, 256,
                            blockIdx.x * 64, idx);
    else
        gemmN64<true, false>(h0 + koff, HH, W_hh + koff, HH,
                             g_gh + ks * BB * 3 * HH, 3 * HH, 256,
                             blockIdx.x * 64, nullptr);
}

// u partials: grid (8 n-tiles, 4 k-splits) = 32 blocks
__global__ void __launch_bounds__(128) k_u(const float* __restrict__ Wa) {
    const int ks = blockIdx.y;
    gemmN64<false, false>(g_A + ks * 128, 1024,
                          Wa + (size_t)(ks * 128) * HH, HH,
                          g_upart + ks * BB * HH, HH,
                          128, blockIdx.x * 64, nullptr);
}

// ---------------- GRU gate combine (sums k-split partials, adds biases) ----
__global__ void k_gates(const float* __restrict__ h0,
                        const float* __restrict__ b_ih, const float* __restrict__ b_hh,
                        float* __restrict__ out_hidden) {
    int i = blockIdx.x * 256 + threadIdx.x;
    int b = i >> 9, h = i & 511;
    const int P = BB * 3 * HH;
    int base = b * 1536 + h;
    float gir = g_gi[base]          + g_gi[P + base]          + b_ih[h];
    float ghr = g_gh[base]          + g_gh[P + base]          + b_hh[h];
    float giz = g_gi[base + 512]    + g_gi[P + base + 512]    + b_ih[512 + h];
    float ghz = g_gh[base + 512]    + g_gh[P + base + 512]    + b_hh[512 + h];
    float gin = g_gi[base + 1024]   + g_gi[P + base + 1024]   + b_ih[1024 + h];
    float ghn = g_gh[base + 1024]   + g_gh[P + base + 1024]   + b_hh[1024 + h];
    float r = 1.f / (1.f + __expf(-(gir + ghr)));
    float z = 1.f / (1.f + __expf(-(giz + ghz)));
    float n = tanhf(gin + r * ghn);
    float hv = (1.f - z) * n + z * h0[b * HH + h];
    g_A[b * 1024 + h] = hv;
    out_hidden[b * HH + h] = hv;
}

// ---------------- classifier tile, tf32 MMA: 64x128, 128 thr ---------------
__device__ __forceinline__ void cls_tf32(float* __restrict__ smbase,
                                         const float* __restrict__ A,
                                         const float* __restrict__ W,
                                         float* __restrict__ C, int n0, int ntile) {
    float (*As)[16][68]  = (float(*)[16][68])smbase;             // [k][m]
    float (*Bs)[16][132] = (float(*)[16][132])(smbase + 2176);   // [k][n]
    const int tid = threadIdx.x;
    const int wid = tid >> 5, lane = tid & 31;
    const int gid = lane >> 2, tig = lane & 3;
    const int wm = (wid >> 1) * 32;   // 0 or 32
    const int wn = (wid & 1) * 64;    // 0 or 64

    float d[2][8][4];
#pragma unroll
    for (int ms = 0; ms < 2; ms++)
#pragma unroll
        for (int nc = 0; nc < 8; nc++)
#pragma unroll
            for (int j = 0; j < 4; j++) d[ms][nc][j] = 0.f;

    float4 ra[2], rb[4];
    auto ldG = [&](int k0) {
#pragma unroll
        for (int r = 0; r < 2; r++) {
            int i = tid + r * 128;
            int m = i >> 2, kq = (i & 3) * 4;
            ra[r] = *(const float4*)(A + (size_t)m * 1024 + k0 + kq);
        }
#pragma unroll
        for (int r = 0; r < 4; r++) {
            int i = tid + r * 128;
            int n = i >> 2, kq = (i & 3) * 4;
            rb[r] = *(const float4*)(W + (size_t)(n0 + n) * 1024 + k0 + kq);
        }
    };
    auto stS = [&](int buf) {
#pragma unroll
        for (int r = 0; r < 2; r++) {
            int i = tid + r * 128;
            int m = i >> 2, kq = (i & 3) * 4;
            As[buf][kq + 0][m] = ra[r].x; As[buf][kq + 1][m] = ra[r].y;
            As[buf][kq + 2][m] = ra[r].z; As[buf][kq + 3][m] = ra[r].w;
        }
#pragma unroll
        for (int r = 0; r < 4; r++) {
            int i = tid + r * 128;
            int n = i >> 2, kq = (i & 3) * 4;
            Bs[buf][kq + 0][n] = rb[r].x; Bs[buf][kq + 1][n] = rb[r].y;
            Bs[buf][kq + 2][n] = rb[r].z; Bs[buf][kq + 3][n] = rb[r].w;
        }
    };

    ldG(0);
    stS(0);
    __syncthreads();
#pragma unroll 1
    for (int t = 0; t < ntile; t++) {
        const int cur = t & 1;
        if (t + 1 < ntile) ldG((t + 1) * 16);
#pragma unroll
        for (int k8 = 0; k8 < 16; k8 += 8) {
            u32 a[2][4];
#pragma unroll
            for (int ms = 0; ms < 2; ms++) {
                int m0 = wm + ms * 16;
                a[ms][0] = f2tf(As[cur][k8 + tig][m0 + gid]);
                a[ms][1] = f2tf(As[cur][k8 + tig][m0 + gid + 8]);
                a[ms][2] = f2tf(As[cur][k8 + tig + 4][m0 + gid]);
                a[ms][3] = f2tf(As[cur][k8 + tig + 4][m0 + gid + 8]);
            }
#pragma unroll
            for (int nc = 0; nc < 8; nc++) {
                int nb = wn + nc * 8;
                u32 b0 = f2tf(Bs[cur][k8 + tig][nb + gid]);
                u32 b1 = f2tf(Bs[cur][k8 + tig + 4][nb + gid]);
                MMA_TF32(d[0][nc][0], d[0][nc][1], d[0][nc][2], d[0][nc][3],
                         a[0][0], a[0][1], a[0][2], a[0][3], b0, b1);
                MMA_TF32(d[1][nc][0], d[1][nc][1], d[1][nc][2], d[1][nc][3],
                         a[1][0], a[1][1], a[1][2], a[1][3], b0, b1);
            }
        }
        if (t + 1 < ntile) stS(cur ^ 1);
        __syncthreads();
    }

#pragma unroll
    for (int ms = 0; ms < 2; ms++) {
        int m0 = wm + ms * 16 + gid;
#pragma unroll
        for (int nc = 0; nc < 8; nc++) {
            int n = n0 + wn + nc * 8 + tig * 2;
            *(float2*)(C + (size_t)m0 * VV + n) =
                make_float2(d[ms][nc][0], d[ms][nc][1]);
            *(float2*)(C + (size_t)(m0 + 8) * VV + n) =
                make_float2(d[ms][nc][2], d[ms][nc][3]);
        }
    }
}

// ---------------- attention body, 128 thr, 2 rows/warp/iter ----------------
__device__ __forceinline__ void attn_body128(float* __restrict__ sm,
                                             const float* __restrict__ enc, int abid) {
    const int sp = abid & (NSPLIT - 1);
    const int b = abid >> 5;                          // NSPLIT = 32
    const int t = threadIdx.x;
    const int wid = t >> 5, lane = t & 31;
    float* su = sm;                                   // 512
    float (*sctx)[HH] = (float(*)[HH])(sm + 512);     // 4*512
    float* sml = sm + 512 + 4 * HH;                   // 8

    const float* up = g_upart + b * HH;
#pragma unroll
    for (int r = 0; r < 4; r++) {
        int h = t + r * 128;
        su[h] = up[h] + up[BB * HH + h] + up[2 * BB * HH + h] + up[3 * BB * HH + h];
    }
    __syncthreads();

    float4 u4[4];
#pragma unroll
    for (int j = 0; j < 4; j++) u4[j] = ((const float4*)su)[lane + 32 * j];

    float m = -INFINITY, l = 0.f;
    float4 acc[4];
#pragma unroll
    for (int j = 0; j < 4; j++) acc[j] = make_float4(0.f, 0.f, 0.f, 0.f);

    const int s0 = sp * SPLIT_S;                      // SPLIT_S = 64
    // warp wid handles rows s0 + it*8 + wid*2 + {0,1}, 8 iterations
    float4 va[4], vb[4];
    {
        const float4* r0 = (const float4*)(enc + ((size_t)(s0 + wid * 2) * BB + b) * HH);
        const float4* r1 = (const float4*)(enc + ((size_t)(s0 + wid * 2 + 1) * BB + b) * HH);
#pragma unroll
        for (int j = 0; j < 4; j++) { va[j] = r0[lane + 32 * j]; vb[j] = r1[lane + 32 * j]; }
    }

#pragma unroll 1
    for (int it = 0; it < SPLIT_S / 8; it++) {        // 8 iterations
        float4 na[4], nb[4];
        if (it + 1 < SPLIT_S / 8) {
            int row = s0 + (it + 1) * 8 + wid * 2;
            const float4* r0 = (const float4*)(enc + ((size_t)row * BB + b) * HH);
            const float4* r1 = (const float4*)(enc + ((size_t)(row + 1) * BB + b) * HH);
#pragma unroll
            for (int j = 0; j < 4; j++) { na[j] = r0[lane + 32 * j]; nb[j] = r1[lane + 32 * j]; }
        } else {
#pragma unroll
            for (int j = 0; j < 4; j++) {
                na[j] = make_float4(0.f, 0.f, 0.f, 0.f);
                nb[j] = make_float4(0.f, 0.f, 0.f, 0.f);
            }
        }
        float pa = 0.f, pb = 0.f;
#pragma unroll
        for (int j = 0; j < 4; j++) {
            pa += va[j].x * u4[j].x + va[j].y * u4[j].y + va[j].z * u4[j].z + va[j].w * u4[j].w;
            pb += vb[j].x * u4[j].x + vb[j].y * u4[j].y + vb[j].z * u4[j].z + vb[j].w * u4[j].w;
        }
#pragma unroll
        for (int o = 16; o; o >>= 1) {
            pa += __shfl_xor_sync(0xffffffffu, pa, o);
            pb += __shfl_xor_sync(0xffffffffu, pb, o);
        }

        float nm = fmaxf(m, fmaxf(pa, pb));
        float sc = __expf(m - nm);
        float wa = __expf(pa - nm);
        float wb = __expf(pb - nm);
        l = l * sc + wa + wb;
#pragma unroll
        for (int j = 0; j < 4; j++) {
            acc[j].x = acc[j].x * sc + wa * va[j].x + wb * vb[j].x;
            acc[j].y = acc[j].y * sc + wa * va[j].y + wb * vb[j].y;
            acc[j].z = acc[j].z * sc + wa * va[j].z + wb * vb[j].z;
            acc[j].w = acc[j].w * sc + wa * va[j].w + wb * vb[j].w;
        }
        m = nm;
#pragma unroll
        for (int j = 0; j < 4; j++) { va[j] = na[j]; vb[j] = nb[j]; }
    }

#pragma unroll
    for (int j = 0; j < 4; j++) ((float4*)sctx[wid])[lane + 32 * j] = acc[j];
    if (lane == 0) { sml[wid * 2] = m; sml[wid * 2 + 1] = l; }
    __syncthreads();

    float M = -INFINITY;
#pragma unroll
    for (int w = 0; w < 4; w++) M = fmaxf(M, sml[w * 2]);
    float L = 0.f, c[4] = {0.f, 0.f, 0.f, 0.f};
#pragma unroll
    for (int w = 0; w < 4; w++) {
        float e = __expf(sml[w * 2] - M);
        L += e * sml[w * 2 + 1];
#pragma unroll
        for (int r = 0; r < 4; r++) c[r] += e * sctx[w][t + r * 128];
    }
    size_t base = ((size_t)sp * BB + b) * HH;
#pragma unroll
    for (int r = 0; r < 4; r++) g_pctx[base + t + r * 128] = c[r];
    if (t == 0) {
        g_pml[(sp * BB + b) * 2] = M;
        g_pml[(sp * BB + b) * 2 + 1] = L;
    }
}

// ---------------- mega: 250 tf32 cls_h tiles FIRST, then attention ---------
__global__ void __launch_bounds__(128) k_mega(const float* __restrict__ enc,
                                              const float* __restrict__ W_cls,
                                              float* __restrict__ out) {
    __shared__ __align__(16) float sm[6400];   // 25.6 KB union
    if (blockIdx.x < NCLS_TILES)
        cls_tf32(sm, g_A, W_cls, out, blockIdx.x * 128, 32);   // K = 512 (h-half)
    else
        attn_body128(sm, enc, blockIdx.x - NCLS_TILES);
}

// ---------------- ctx-half of classifier: tf32, K=512 -> g_p0 --------------
__global__ void __launch_bounds__(128) k_cls_ctx(const float* __restrict__ W_cls) {
    __shared__ __align__(16) float sm[6400];
    cls_tf32(sm, g_A + 512, W_cls + 512, g_p0, blockIdx.x * 128, 32);
}

// ---------------- combine splits (32) ----------------
__global__ void k_comb() {
    int b = blockIdx.x, t = threadIdx.x;      // 256 threads
    __shared__ float sm[NSPLIT], sl[NSPLIT];
    if (t < NSPLIT) {
        sm[t] = g_pml[(t * BB + b) * 2];
        sl[t] = g_pml[(t * BB + b) * 2 + 1];
    }
    __syncthreads();
    float M = -INFINITY;
#pragma unroll
    for (int i = 0; i < NSPLIT; i++) M = fmaxf(M, sm[i]);
    float L = 0.f;
#pragma unroll
    for (int i = 0; i < NSPLIT; i++) L += sl[i] * __expf(sm[i] - M);
    float inv = 1.f / L;
    float o0 = 0.f, o1 = 0.f;
#pragma unroll 8
    for (int i = 0; i < NSPLIT; i++) {
        float w = __expf(sm[i] - M);
        size_t base = ((size_t)i * BB + b) * HH;
        o0 += w * g_pctx[base + t];
        o1 += w * g_pctx[base + t + 256];
    }
    g_A[b * 1024 + 512 + t] = o0 * inv;
    g_A[b * 1024 + 512 + t + 256] = o1 * inv;
}

// ---------------- fused log-softmax over (out + p0 + bias), online 2-pass ---
__global__ void k_lsefix(float* __restrict__ out, const float* __restrict__ b_cls) {
    const int b = blockIdx.x, t = threadIdx.x;   // 1024 threads
    float4* rowO = (float4*)(out + (size_t)b * VV);
    const float4* rowP0 = (const float4*)(g_p0 + (size_t)b * VV);
    const float4* bias4 = (const float4*)b_cls;
    __shared__ float redm[32], redl[32];
    __shared__ float sC;
    const int lane = t & 31, wid = t >> 5;

    // pass 1: online max + sum
    float m = -INFINITY, l = 0.f;
    for (int i = t; i < VV / 4; i += 1024) {
        float4 v = rowO[i], a = rowP0[i], bb = bias4[i];
        float x[4] = {v.x + a.x + bb.x, v.y + a.y + bb.y,
                      v.z + a.z + bb.z, v.w + a.w + bb.w};
#pragma unroll
        for (int j = 0; j < 4; j++) {
            float nm = fmaxf(m, x[j]);
            l = l * __expf(m - nm) + __expf(x[j] - nm);
            m = nm;
        }
    }
#pragma unroll
    for (int o = 16; o; o >>= 1) {
        float om = __shfl_xor_sync(0xffffffffu, m, o);
        float ol = __shfl_xor_sync(0xffffffffu, l, o);
        float nm = fmaxf(m, om);
        l = l * __expf(m - nm) + ol * __expf(om - nm);
        m = nm;
    }
    if (lane == 0) { redm[wid] = m; redl[wid] = l; }
    __syncthreads();
    if (t < 32) {
        float qm = redm[t], ql = redl[t];
#pragma unroll
        for (int o = 16; o; o >>= 1) {
            float om = __shfl_xor_sync(0xffffffffu, qm, o);
            float ol = __shfl_xor_sync(0xffffffffu, ql, o);
            float nm = fmaxf(qm, om);
            ql = ql * __expf(qm - nm) + ol * __expf(om - nm);
            qm = nm;
        }
        if (t == 0) sC = qm + logf(ql);
    }
    __syncthreads();
    const float c = sC;

    // pass 2: write
    for (int i = t; i < VV / 4; i += 1024) {
        float4 v = rowO[i], a = rowP0[i], bb = bias4[i];
        v.x = v.x + a.x + bb.x - c;
        v.y = v.y + a.y + bb.y - c;
        v.z = v.z + a.z + bb.z - c;
        v.w = v.w + a.w + bb.w - c;
        rowO[i] = v;
    }
}

// ---------------- launch ----------------
extern "C" void kernel_launch(void* const* d_in, const int* in_sizes, int n_in,
                              void* d_out, int out_size) {
    const int*   dec_inputs = (const int*)d_in[0];
    const float* enc        = (const float*)d_in[1];
    const float* h0         = (const float*)d_in[2];
    const float* emb        = (const float*)d_in[3];
    const float* W_ih       = (const float*)d_in[4];
    const float* W_hh       = (const float*)d_in[5];
    const float* b_ih       = (const float*)d_in[6];
    const float* b_hh       = (const float*)d_in[7];
    const float* W_attn     = (const float*)d_in[8];
    const float* b_attn     = (const float*)d_in[9];   // cancels in softmax
    const float* W_cls      = (const float*)d_in[10];
    const float* b_cls      = (const float*)d_in[11];
    (void)b_attn; (void)in_sizes; (void)n_in; (void)out_size;

    float* out        = (float*)d_out;
    float* out_hidden = (float*)d_out + (size_t)BB * VV;

    k_gru<<<dim3(24, 2, 2), 128>>>(dec_inputs, emb, h0, W_ih, W_hh);
    k_gates<<<BB * HH / 256, 256>>>(h0, b_ih, b_hh, out_hidden);
    k_u<<<dim3(8, 4), 128>>>(W_attn);
    k_mega<<<NCLS_TILES + NATTN, 128>>>(enc, W_cls, out);
    k_comb<<<BB, 256>>>();
    k_cls_ctx<<<NCLS_TILES, 128>>>(W_cls);
    k_lsefix<<<BB, 1024>>>(out, b_cls);
}